// round 7
// baseline (speedup 1.0000x reference)
#include <cuda_runtime.h>

// SliceLSTM persistent kernel, round 7: full-width compute (2 warps/SMSP).
// B=64, T=512, S=4, DIN=64, H=128, HTOT=512.
// 128 CTAs x 256 threads, all co-resident. Dataflow sync (no global barriers),
// parity double-buffered h/act/partials, all cross-CTA data via L2 (.cg).
// P1: 1b x 4c per thread, K=192 (no k-split). P2: 4b x 8c per thread, K=64.

#define NCTA 128
#define NTHR 256
#define LD1 193
#define LD2 65

#define OFF_W1 0        // 192 x 16
#define OFF_B1 3072     // 16
#define OFF_W2 3088     // 64 x 128
#define OFF_A1 11280    // 64 x 193  (k<64: x, k>=64: h)
#define OFF_A2 23632    // 64 x 65
#define SMEM_BYTES 118784   // 116KB: forces 1 CTA/SM

__device__ float g_hbuf[2][64 * 512];            // [parity][b][c]
__device__ float g_act[2][4 * 64 * 512];         // [parity][gate][b][c]
__device__ float g_part[2][NCTA * 64 * 128];     // [parity][blk][b][cl]
__device__ unsigned g_actflag[NCTA * 8];         // stride 32B
__device__ unsigned g_pcnt[4 * 64];              // stride 256B
__device__ unsigned g_hcnt[4 * 64];

static __device__ __forceinline__ unsigned long long pk2(float v) {
    unsigned long long r;
    asm("mov.b64 %0, {%1, %1};" : "=l"(r) : "f"(v));
    return r;
}
static __device__ __forceinline__ void unp2(unsigned long long v, float& lo, float& hi) {
    asm("mov.b64 {%0, %1}, %2;" : "=f"(lo), "=f"(hi) : "l"(v));
}
static __device__ __forceinline__ void fma2(unsigned long long& d,
                                            unsigned long long a, unsigned long long b) {
    asm("fma.rn.f32x2 %0, %1, %2, %0;" : "+l"(d) : "l"(a), "l"(b));
}
static __device__ __forceinline__ float sigf(float x)  { return 1.0f / (1.0f + __expf(-x)); }
static __device__ __forceinline__ float tanhe(float x) {
    float e = __expf(2.0f * x);
    return 1.0f - 2.0f / (e + 1.0f);
}
static __device__ __forceinline__ unsigned ldacq(const unsigned* p) {
    unsigned v;
    asm volatile("ld.acquire.gpu.global.u32 %0, [%1];" : "=r"(v) : "l"(p) : "memory");
    return v;
}
static __device__ __forceinline__ void strel(unsigned* p, unsigned v) {
    asm volatile("st.release.gpu.global.u32 [%0], %1;" :: "l"(p), "r"(v) : "memory");
}
static __device__ __forceinline__ void redrel(unsigned* p) {
    asm volatile("red.release.gpu.global.add.u32 [%0], 1;" :: "l"(p) : "memory");
}

__global__ void zero_kernel() {
    int i = blockIdx.x * blockDim.x + threadIdx.x;
    int n = blockDim.x * gridDim.x;
    for (int j = i; j < 64 * 512; j += n) g_hbuf[0][j] = 0.0f;
    for (int j = i; j < NCTA * 8; j += n) g_actflag[j] = 0u;
    for (int j = i; j < 4 * 64; j += n) { g_pcnt[j] = 0u; g_hcnt[j] = 0u; }
}

__global__ void __launch_bounds__(NTHR, 1)
slstm_kernel(const float* __restrict__ x,       // (64, 512, 256)
             const float* __restrict__ Ws,      // (4, 64, 512)
             const float* __restrict__ Us,      // (4, 128, 512)
             const float* __restrict__ biases,  // (4, 512)
             const float* __restrict__ Wc,      // (512, 2048)
             const float* __restrict__ bc,      // (2048,)
             float* __restrict__ out)           // hseq | h_t | c_t
{
    extern __shared__ float sm[];
    float* sW1 = sm + OFF_W1;
    float* sB1 = sm + OFF_B1;
    float* sW2 = sm + OFF_W2;
    float* sA1 = sm + OFF_A1;
    float* sA2 = sm + OFF_A2;

    const int tid = threadIdx.x;
    const int cta = blockIdx.x;

    // P1 role: slice s1, 16 stage-1 cols at u0 (single gate)
    const int s1    = cta >> 5;
    const int u0    = (cta & 31) * 16;
    const int gate1 = u0 >> 7;
    const int col0  = s1 * 128 + (u0 & 127);
    const int p1b   = tid >> 2;          // batch 0..63
    const int p1cg  = tid & 3;           // 4-col group

    // P2 role: gate g2, col-tile ct2 (128 cols), K-chunk kc2 (64 rows)
    const int g2  = cta >> 5;
    const int ct2 = (cta >> 3) & 3;
    const int kc2 = cta & 7;
    const int c20 = ct2 * 128;
    const int k20 = kc2 * 64;
    const int p2b0 = (tid & 15) * 4;     // 4-batch group
    const int p2cc = (tid >> 4) * 8;     // 8-col group
    // producers of act[g2][:, k20..k20+64): 4 P1 CTAs
    const int prod = ((kc2 >> 1) << 5) | (g2 << 3) | ((kc2 & 1) << 2);

    // P3 role: CTA owns col-tile ct3 (128 cols) x 2 batches (b0, b0+1)
    const int ct3 = cta & 3;
    const int b0  = (cta >> 2) * 2;
    const int boff = (tid >> 5) & 1;     // tid<64: which of the 2 batches
    const int c4   = (tid & 31) * 4;     // 4 cols within the tile

    // ---- persistent weights ----
    for (int i = tid; i < 192 * 16; i += NTHR) {
        int k = i >> 4, c = i & 15;
        sW1[i] = (k < 64) ? Ws[s1 * (64 * 512) + k * 512 + u0 + c]
                          : Us[s1 * (128 * 512) + (k - 64) * 512 + u0 + c];
    }
    if (tid < 16) sB1[tid] = biases[s1 * 512 + u0 + tid];
    for (int i = tid; i < 64 * 128; i += NTHR) {
        int k = i >> 7, c = i & 127;
        sW2[k * 128 + c] = Wc[(k20 + k) * 2048 + g2 * 512 + c20 + c];
    }

    // P3 biases + state
    float4 bi = {0,0,0,0}, bf = {0,0,0,0}, bg4 = {0,0,0,0}, bo = {0,0,0,0};
    float4 creg = {0,0,0,0}, hlast = {0,0,0,0};
    if (tid < 64) {
        const int cc = ct3 * 128 + c4;
        bi  = *reinterpret_cast<const float4*>(&bc[cc]);
        bf  = *reinterpret_cast<const float4*>(&bc[512 + cc]);
        bg4 = *reinterpret_cast<const float4*>(&bc[1024 + cc]);
        bo  = *reinterpret_cast<const float4*>(&bc[1536 + cc]);
    }
    // stage x(t=0)
    for (int i = tid; i < 256; i += NTHR) {
        int b = i & 63, q = i >> 6;
        const float4* src = reinterpret_cast<const float4*>(
            &x[b * (512 * 256) + s1 * 64 + q * 16]);
        float* dst = &sA1[b * LD1 + q * 16];
        #pragma unroll
        for (int j = 0; j < 4; ++j) {
            float4 v = __ldg(src + j);
            dst[j * 4 + 0] = v.x; dst[j * 4 + 1] = v.y;
            dst[j * 4 + 2] = v.z; dst[j * 4 + 3] = v.w;
        }
    }

    for (int t = 0; t < 512; ++t) {
        const int p  = t & 1;
        const int pn = p ^ 1;

        // ================= P1: wait h, stage h, block-diag GEMM =================
        if (tid == 0) {
            const unsigned need = 32u * (unsigned)t;
            while (ldacq(&g_hcnt[s1 * 64]) < need) {}
        }
        __syncthreads();
        {
            const float* hb = g_hbuf[p];
            for (int i = tid; i < 256; i += NTHR) {
                int b = i & 63, q = i >> 6;
                const float4* src = reinterpret_cast<const float4*>(
                    &hb[b * 512 + s1 * 128 + q * 32]);
                float* dst = &sA1[b * LD1 + 64 + q * 32];
                #pragma unroll
                for (int j = 0; j < 8; ++j) {
                    float4 v = __ldcg(src + j);
                    dst[j * 4 + 0] = v.x; dst[j * 4 + 1] = v.y;
                    dst[j * 4 + 2] = v.z; dst[j * 4 + 3] = v.w;
                }
            }
        }
        __syncthreads();
        {
            // 1b x 4c per thread, all 256 threads, K=192
            const float* ap = sA1 + p1b * LD1;
            const float* wp = sW1 + p1cg * 4;
            unsigned long long acc0 = 0ULL, acc1 = 0ULL;
            #pragma unroll 8
            for (int k = 0; k < 192; ++k) {
                const ulonglong2 w = *reinterpret_cast<const ulonglong2*>(wp + k * 16);
                const unsigned long long a = pk2(ap[k]);
                fma2(acc0, a, w.x);
                fma2(acc1, a, w.y);
            }
            float v0, v1, v2, v3;
            unp2(acc0, v0, v1);
            unp2(acc1, v2, v3);
            v0 += sB1[p1cg * 4 + 0];
            v1 += sB1[p1cg * 4 + 1];
            v2 += sB1[p1cg * 4 + 2];
            v3 += sB1[p1cg * 4 + 3];
            if (gate1 == 2) { v0 = tanhe(v0); v1 = tanhe(v1); v2 = tanhe(v2); v3 = tanhe(v3); }
            else           { v0 = sigf(v0);  v1 = sigf(v1);  v2 = sigf(v2);  v3 = sigf(v3);  }
            __stcg(reinterpret_cast<float4*>(
                       &g_act[p][gate1 * 32768 + p1b * 512 + col0 + p1cg * 4]),
                   make_float4(v0, v1, v2, v3));
        }
        __syncthreads();
        if (tid == 0) {
            __threadfence();
            strel(&g_actflag[cta * 8], (unsigned)(t + 1));
        }

        // ================= P2: wait producers, stage act, connector GEMM =================
        if (tid < 4) {
            const unsigned need = (unsigned)(t + 1);
            const unsigned* f = &g_actflag[(prod + tid) * 8];
            while (ldacq(f) < need) {}
        }
        __syncthreads();
        {
            const float* ab = g_act[p] + g2 * 32768;
            for (int i = tid; i < 256; i += NTHR) {
                int b = i & 63, q = i >> 6;
                const float4* src = reinterpret_cast<const float4*>(
                    &ab[b * 512 + k20 + q * 16]);
                float* dst = &sA2[b * LD2 + q * 16];
                #pragma unroll
                for (int j = 0; j < 4; ++j) {
                    float4 v = __ldcg(src + j);
                    dst[j * 4 + 0] = v.x; dst[j * 4 + 1] = v.y;
                    dst[j * 4 + 2] = v.z; dst[j * 4 + 3] = v.w;
                }
            }
        }
        __syncthreads();
        {
            // 4b x 8c per thread, all 256 threads, K=64
            unsigned long long acc[4][4];
            #pragma unroll
            for (int i = 0; i < 4; ++i)
                #pragma unroll
                for (int j = 0; j < 4; ++j) acc[i][j] = 0ULL;
            const float* wbase = sW2 + p2cc;
            #pragma unroll 4
            for (int k = 0; k < 64; ++k) {
                const float* wr = wbase + k * 128;
                const ulonglong2 wA = *reinterpret_cast<const ulonglong2*>(wr);
                const ulonglong2 wB = *reinterpret_cast<const ulonglong2*>(wr + 4);
                #pragma unroll
                for (int i = 0; i < 4; ++i) {
                    const unsigned long long a = pk2(sA2[(p2b0 + i) * LD2 + k]);
                    fma2(acc[i][0], a, wA.x); fma2(acc[i][1], a, wA.y);
                    fma2(acc[i][2], a, wB.x); fma2(acc[i][3], a, wB.y);
                }
            }
            float* pp = g_part[p] + cta * 8192 + p2cc;
            #pragma unroll
            for (int i = 0; i < 4; ++i) {
                float q0,q1,q2,q3,q4,q5,q6,q7;
                unp2(acc[i][0], q0, q1); unp2(acc[i][1], q2, q3);
                unp2(acc[i][2], q4, q5); unp2(acc[i][3], q6, q7);
                float4* d = reinterpret_cast<float4*>(pp + (p2b0 + i) * 128);
                __stcg(d + 0, make_float4(q0, q1, q2, q3));
                __stcg(d + 1, make_float4(q4, q5, q6, q7));
            }
        }
        __syncthreads();
        if (tid == 0) {
            __threadfence();
            redrel(&g_pcnt[ct2 * 64]);
            const unsigned need = 32u * (unsigned)(t + 1);
            while (ldacq(&g_pcnt[ct3 * 64]) < need) {}
        }
        __syncthreads();

        // ================= P3: gather partials + cell update; x prefetch =================
        if (tid < 64) {
            const int bb = b0 + boff;
            float4 ai = {0,0,0,0}, af = {0,0,0,0}, ag = {0,0,0,0}, ao = {0,0,0,0};
            const float* pb = g_part[p] + bb * 128 + c4;
            #pragma unroll
            for (int kc = 0; kc < 8; ++kc) {
                float4 v;
                v = __ldcg(reinterpret_cast<const float4*>(pb + (0 * 32 + ct3 * 8 + kc) * 8192));
                ai.x += v.x; ai.y += v.y; ai.z += v.z; ai.w += v.w;
                v = __ldcg(reinterpret_cast<const float4*>(pb + (1 * 32 + ct3 * 8 + kc) * 8192));
                af.x += v.x; af.y += v.y; af.z += v.z; af.w += v.w;
                v = __ldcg(reinterpret_cast<const float4*>(pb + (2 * 32 + ct3 * 8 + kc) * 8192));
                ag.x += v.x; ag.y += v.y; ag.z += v.z; ag.w += v.w;
                v = __ldcg(reinterpret_cast<const float4*>(pb + (3 * 32 + ct3 * 8 + kc) * 8192));
                ao.x += v.x; ao.y += v.y; ao.z += v.z; ao.w += v.w;
            }
            float4 hn;
            {
                float iv = sigf(ai.x + bi.x), fv = sigf(af.x + bf.x);
                float gv = tanhe(ag.x + bg4.x), ov = sigf(ao.x + bo.x);
                creg.x = fv * creg.x + iv * gv; hn.x = ov * tanhe(creg.x);
                iv = sigf(ai.y + bi.y); fv = sigf(af.y + bf.y);
                gv = tanhe(ag.y + bg4.y); ov = sigf(ao.y + bo.y);
                creg.y = fv * creg.y + iv * gv; hn.y = ov * tanhe(creg.y);
                iv = sigf(ai.z + bi.z); fv = sigf(af.z + bf.z);
                gv = tanhe(ag.z + bg4.z); ov = sigf(ao.z + bo.z);
                creg.z = fv * creg.z + iv * gv; hn.z = ov * tanhe(creg.z);
                iv = sigf(ai.w + bi.w); fv = sigf(af.w + bf.w);
                gv = tanhe(ag.w + bg4.w); ov = sigf(ao.w + bo.w);
                creg.w = fv * creg.w + iv * gv; hn.w = ov * tanhe(creg.w);
            }
            hlast = hn;
            const int cc = ct3 * 128 + c4;
            __stcg(reinterpret_cast<float4*>(&g_hbuf[pn][bb * 512 + cc]), hn);
            *reinterpret_cast<float4*>(&out[bb * (512 * 512) + t * 512 + cc]) = hn;
        } else if (t + 1 < 512) {
            // x prefetch for t+1 (threads 64..255)
            for (int i = tid - 64; i < 256; i += 192) {
                int b = i & 63, q = i >> 6;
                const float4* src = reinterpret_cast<const float4*>(
                    &x[b * (512 * 256) + (t + 1) * 256 + s1 * 64 + q * 16]);
                float* dst = &sA1[b * LD1 + q * 16];
                #pragma unroll
                for (int j = 0; j < 4; ++j) {
                    float4 v = __ldg(src + j);
                    dst[j * 4 + 0] = v.x; dst[j * 4 + 1] = v.y;
                    dst[j * 4 + 2] = v.z; dst[j * 4 + 3] = v.w;
                }
            }
        }
        __syncthreads();
        if (tid == 0) {
            __threadfence();
            redrel(&g_hcnt[ct3 * 64]);
        }
    }

    if (tid < 64) {
        const int bb = b0 + boff;
        const int cc = ct3 * 128 + c4;
        *reinterpret_cast<float4*>(&out[16777216 + bb * 512 + cc]) = hlast;
        *reinterpret_cast<float4*>(&out[16777216 + 32768 + bb * 512 + cc]) = creg;
    }
}

extern "C" void kernel_launch(void* const* d_in, const int* in_sizes, int n_in,
                              void* d_out, int out_size) {
    const float* x      = (const float*)d_in[0];
    const float* Ws     = (const float*)d_in[1];
    const float* Us     = (const float*)d_in[2];
    const float* biases = (const float*)d_in[3];
    const float* Wc     = (const float*)d_in[4];
    const float* bc     = (const float*)d_in[5];
    float* out = (float*)d_out;
    (void)in_sizes; (void)n_in; (void)out_size;

    zero_kernel<<<32, 256>>>();
    cudaFuncSetAttribute(slstm_kernel, cudaFuncAttributeMaxDynamicSharedMemorySize,
                         SMEM_BYTES);
    slstm_kernel<<<NCTA, NTHR, SMEM_BYTES>>>(x, Ws, Us, biases, Wc, bc, out);
}

// round 8
// speedup vs baseline: 1.1232x; 1.1232x over previous
#include <cuda_runtime.h>
#include <cstdint>

// SliceLSTM persistent kernel, round 8: cluster-of-4 + DSMEM act exchange.
// B=64, T=512, S=4, DIN=64, H=128, HTOT=512.
// 128 CTAs x 256 threads, clusters of 4 = (gate g, K-chunk kc); rank r in the
// cluster computes stage-1 act block r (16 cols) AND connector col-tile r.
// Act is exchanged inside the cluster via st.shared::cluster + split cluster
// barriers (no global act buffer). Partials and h still flow via L2 counters.

#define NCTA 128
#define NTHR 256

// shared layout (float offsets)
#define OFF_W1  0        // 192 x 16
#define OFF_B1  3072     // 16
#define OFF_W2  3088     // 64 x 128
#define OFF_A1  11280    // 64 x 193  (k<64: x, k>=64: h), b-major
#define LD1     193
#define OFF_ACT 23632    // 64 x 68, k-major: sAct[k][b]
#define LDA     68
#define SMEM_BYTES 116480  // 113.75KB: 2 CTAs would need 227.5KB > 227KB -> 1/SM

__device__ float g_hbuf[2][64 * 512];            // [parity][b][c]
__device__ float g_part[2][NCTA * 64 * 128];     // [parity][blk][b][cl]
__device__ unsigned g_pcnt[4 * 64];              // per col-tile, stride 256B
__device__ unsigned g_hcnt[4 * 64];

static __device__ __forceinline__ unsigned long long pk2(float v) {
    unsigned long long r;
    asm("mov.b64 %0, {%1, %1};" : "=l"(r) : "f"(v));
    return r;
}
static __device__ __forceinline__ void unp2(unsigned long long v, float& lo, float& hi) {
    asm("mov.b64 {%0, %1}, %2;" : "=f"(lo), "=f"(hi) : "l"(v));
}
static __device__ __forceinline__ void fma2(unsigned long long& d,
                                            unsigned long long a, unsigned long long b) {
    asm("fma.rn.f32x2 %0, %1, %2, %0;" : "+l"(d) : "l"(a), "l"(b));
}
static __device__ __forceinline__ float sigf(float x)  { return 1.0f / (1.0f + __expf(-x)); }
static __device__ __forceinline__ float tanhe(float x) {
    float e = __expf(2.0f * x);
    return 1.0f - 2.0f / (e + 1.0f);
}
static __device__ __forceinline__ unsigned ldacq(const unsigned* p) {
    unsigned v;
    asm volatile("ld.acquire.gpu.global.u32 %0, [%1];" : "=r"(v) : "l"(p) : "memory");
    return v;
}
static __device__ __forceinline__ void redrel(unsigned* p) {
    asm volatile("red.release.gpu.global.add.u32 [%0], 1;" :: "l"(p) : "memory");
}
static __device__ __forceinline__ uint32_t smem_u32(const void* p) {
    uint32_t a;
    asm("{ .reg .u64 t; cvta.to.shared.u64 t, %1; cvt.u32.u64 %0, t; }"
        : "=r"(a) : "l"(p));
    return a;
}
static __device__ __forceinline__ uint32_t mapa_rank(uint32_t addr, int rank) {
    uint32_t r;
    asm("mapa.shared::cluster.u32 %0, %1, %2;" : "=r"(r) : "r"(addr), "r"(rank));
    return r;
}
static __device__ __forceinline__ void st_cluster(uint32_t addr, float v) {
    asm volatile("st.shared::cluster.f32 [%0], %1;" :: "r"(addr), "f"(v) : "memory");
}
#define CARRIVE() asm volatile("barrier.cluster.arrive.aligned;" ::: "memory")
#define CWAIT()   asm volatile("barrier.cluster.wait.aligned;" ::: "memory")

__global__ void zero_kernel() {
    int i = blockIdx.x * blockDim.x + threadIdx.x;
    int n = blockDim.x * gridDim.x;
    for (int j = i; j < 64 * 512; j += n) g_hbuf[0][j] = 0.0f;
    for (int j = i; j < 4 * 64; j += n) { g_pcnt[j] = 0u; g_hcnt[j] = 0u; }
}

__global__ void __launch_bounds__(NTHR, 1) __cluster_dims__(4, 1, 1)
slstm_kernel(const float* __restrict__ x,       // (64, 512, 256)
             const float* __restrict__ Ws,      // (4, 64, 512)
             const float* __restrict__ Us,      // (4, 128, 512)
             const float* __restrict__ biases,  // (4, 512)
             const float* __restrict__ Wc,      // (512, 2048)
             const float* __restrict__ bc,      // (2048,)
             float* __restrict__ out)           // hseq | h_t | c_t
{
    extern __shared__ float sm[];
    float* sW1  = sm + OFF_W1;
    float* sB1  = sm + OFF_B1;
    float* sW2  = sm + OFF_W2;
    float* sA1  = sm + OFF_A1;
    float* sAct = sm + OFF_ACT;

    const int tid  = threadIdx.x;
    const int cta  = blockIdx.x;
    const int rank = cta & 3;          // cluster rank = act block = P2 col-tile = P3 tile
    const int grp  = cta >> 2;         // 0..31
    const int g    = grp >> 3;         // gate
    const int kc   = grp & 7;          // K-chunk of the connector
    const int s1   = kc >> 1;          // slice this chunk lives in
    // stage-1 weight columns this CTA owns (16 of the 512 gate-cols of slice s1)
    const int wcol0 = g * 128 + (kc & 1) * 64 + rank * 16;

    // Phase-A thread role: 1 batch x 4 cols
    const int pab = tid >> 2;          // batch 0..63
    const int pac = tid & 3;           // 4-col group (cols pac*4.. within the 16)

    // Phase-B thread role: 4 batches x 8 cols
    const int b0 = (tid & 15) * 4;
    const int cc = tid >> 4;           // 0..15

    // P3 role: tile ct3 = rank, batches (grp*2, grp*2+1)
    const int ct3  = rank;
    const int b0p  = grp * 2;
    const int boff = (tid >> 5) & 1;
    const int c4   = (tid & 31) * 4;

    // ---- persistent weights ----
    for (int i = tid; i < 192 * 16; i += NTHR) {
        int k = i >> 4, c = i & 15;
        sW1[i] = (k < 64) ? Ws[s1 * (64 * 512) + k * 512 + wcol0 + c]
                          : Us[s1 * (128 * 512) + (k - 64) * 512 + wcol0 + c];
    }
    if (tid < 16) sB1[tid] = biases[s1 * 512 + wcol0 + tid];
    for (int i = tid; i < 64 * 128; i += NTHR) {
        int k = i >> 7, c = i & 127;
        sW2[k * 128 + c] = Wc[(kc * 64 + k) * 2048 + g * 512 + rank * 128 + c];
    }

    // P3 biases + state
    float4 bi = {0,0,0,0}, bf = {0,0,0,0}, bg4 = {0,0,0,0}, bo = {0,0,0,0};
    float4 creg = {0,0,0,0}, hlast = {0,0,0,0};
    if (tid < 64) {
        const int ccl = ct3 * 128 + c4;
        bi  = *reinterpret_cast<const float4*>(&bc[ccl]);
        bf  = *reinterpret_cast<const float4*>(&bc[512 + ccl]);
        bg4 = *reinterpret_cast<const float4*>(&bc[1024 + ccl]);
        bo  = *reinterpret_cast<const float4*>(&bc[1536 + ccl]);
    }
    // stage x(t=0)
    for (int i = tid; i < 256; i += NTHR) {
        int b = i & 63, q = i >> 6;
        const float4* src = reinterpret_cast<const float4*>(
            &x[b * (512 * 256) + s1 * 64 + q * 16]);
        float* dst = &sA1[b * LD1 + q * 16];
        #pragma unroll
        for (int j = 0; j < 4; ++j) {
            float4 v = __ldg(src + j);
            dst[j * 4 + 0] = v.x; dst[j * 4 + 1] = v.y;
            dst[j * 4 + 2] = v.z; dst[j * 4 + 3] = v.w;
        }
    }
    const uint32_t act_u32 = smem_u32(sAct);

    CARRIVE();   // prime the B-done phase so the first CWAIT below passes

    for (int t = 0; t < 512; ++t) {
        const int p  = t & 1;
        const int pn = p ^ 1;

        // ===== Phase A: wait h, stage h, stage-1 GEMM (16 cols) =====
        if (tid == 0) {
            const unsigned need = 32u * (unsigned)t;
            while (ldacq(&g_hcnt[s1 * 64]) < need) {}
        }
        __syncthreads();
        {
            const float* hb = g_hbuf[p];
            for (int i = tid; i < 256; i += NTHR) {
                int b = i & 63, q = i >> 6;
                const float4* src = reinterpret_cast<const float4*>(
                    &hb[b * 512 + s1 * 128 + q * 32]);
                float* dst = &sA1[b * LD1 + 64 + q * 32];
                #pragma unroll
                for (int j = 0; j < 8; ++j) {
                    float4 v = __ldcg(src + j);
                    dst[j * 4 + 0] = v.x; dst[j * 4 + 1] = v.y;
                    dst[j * 4 + 2] = v.z; dst[j * 4 + 3] = v.w;
                }
            }
        }
        __syncthreads();
        float v0, v1, v2, v3;
        {
            const float* ap = sA1 + pab * LD1;
            const float* wp = sW1 + pac * 4;
            unsigned long long acc0 = 0ULL, acc1 = 0ULL;
            #pragma unroll 8
            for (int k = 0; k < 192; ++k) {
                const ulonglong2 w = *reinterpret_cast<const ulonglong2*>(wp + k * 16);
                const unsigned long long a = pk2(ap[k]);
                fma2(acc0, a, w.x);
                fma2(acc1, a, w.y);
            }
            unp2(acc0, v0, v1);
            unp2(acc1, v2, v3);
            v0 += sB1[pac * 4 + 0];
            v1 += sB1[pac * 4 + 1];
            v2 += sB1[pac * 4 + 2];
            v3 += sB1[pac * 4 + 3];
            if (g == 2) { v0 = tanhe(v0); v1 = tanhe(v1); v2 = tanhe(v2); v3 = tanhe(v3); }
            else        { v0 = sigf(v0);  v1 = sigf(v1);  v2 = sigf(v2);  v3 = sigf(v3);  }
        }
        CWAIT();   // peers finished reading sAct from previous step
        {
            // local + remote act publish, k-major: sAct[lc][b]
            const int lc = rank * 16 + pac * 4;
            float* lp = sAct + lc * LDA + pab;
            lp[0]       = v0;
            lp[LDA]     = v1;
            lp[2 * LDA] = v2;
            lp[3 * LDA] = v3;
            const uint32_t la = act_u32 + ((lc * LDA + pab) << 2);
            #pragma unroll
            for (int r = 0; r < 4; ++r) {
                if (r == rank) continue;
                uint32_t ra = mapa_rank(la, r);
                st_cluster(ra,                v0);
                st_cluster(ra + 4 * LDA,      v1);
                st_cluster(ra + 8 * LDA,      v2);
                st_cluster(ra + 12 * LDA,     v3);
            }
        }
        CARRIVE();   // my act contributions done (release)
        CWAIT();     // full 64-col act chunk present locally

        // ===== Phase B: connector GEMM, K=64 local, 128 cols =====
        {
            unsigned long long acc[4][4];
            #pragma unroll
            for (int i = 0; i < 4; ++i)
                #pragma unroll
                for (int j = 0; j < 4; ++j) acc[i][j] = 0ULL;
            const float* wb = sW2 + cc * 8;
            #pragma unroll 4
            for (int k = 0; k < 64; ++k) {
                const float4 a4 = *reinterpret_cast<const float4*>(&sAct[k * LDA + b0]);
                const ulonglong2 wA = *reinterpret_cast<const ulonglong2*>(wb + k * 128);
                const ulonglong2 wB = *reinterpret_cast<const ulonglong2*>(wb + k * 128 + 4);
                const unsigned long long a0 = pk2(a4.x);
                const unsigned long long a1 = pk2(a4.y);
                const unsigned long long a2 = pk2(a4.z);
                const unsigned long long a3 = pk2(a4.w);
                fma2(acc[0][0], a0, wA.x); fma2(acc[0][1], a0, wA.y);
                fma2(acc[0][2], a0, wB.x); fma2(acc[0][3], a0, wB.y);
                fma2(acc[1][0], a1, wA.x); fma2(acc[1][1], a1, wA.y);
                fma2(acc[1][2], a1, wB.x); fma2(acc[1][3], a1, wB.y);
                fma2(acc[2][0], a2, wA.x); fma2(acc[2][1], a2, wA.y);
                fma2(acc[2][2], a2, wB.x); fma2(acc[2][3], a2, wB.y);
                fma2(acc[3][0], a3, wA.x); fma2(acc[3][1], a3, wA.y);
                fma2(acc[3][2], a3, wB.x); fma2(acc[3][3], a3, wB.y);
            }
            CARRIVE();   // done reading sAct -> peers may overwrite next step
            float* pp = g_part[p] + cta * 8192 + cc * 8;
            #pragma unroll
            for (int i = 0; i < 4; ++i) {
                float q0,q1,q2,q3,q4,q5,q6,q7;
                unp2(acc[i][0], q0, q1); unp2(acc[i][1], q2, q3);
                unp2(acc[i][2], q4, q5); unp2(acc[i][3], q6, q7);
                float4* d = reinterpret_cast<float4*>(pp + (b0 + i) * 128);
                __stcg(d + 0, make_float4(q0, q1, q2, q3));
                __stcg(d + 1, make_float4(q4, q5, q6, q7));
            }
        }
        __syncthreads();
        if (tid == 0) {
            __threadfence();
            redrel(&g_pcnt[rank * 64]);
            const unsigned need = 32u * (unsigned)(t + 1);
            while (ldacq(&g_pcnt[ct3 * 64]) < need) {}
        }
        __syncthreads();

        // ===== P3: gather partials + cell update; x prefetch =====
        if (tid < 64) {
            const int bb = b0p + boff;
            float4 ai = {0,0,0,0}, af = {0,0,0,0}, ag = {0,0,0,0}, ao = {0,0,0,0};
            const float* pb = g_part[p] + bb * 128 + c4;
            #pragma unroll
            for (int q = 0; q < 8; ++q) {
                float4 v;
                v = __ldcg(reinterpret_cast<const float4*>(pb + (((0 * 8 + q) << 2) | ct3) * 8192));
                ai.x += v.x; ai.y += v.y; ai.z += v.z; ai.w += v.w;
                v = __ldcg(reinterpret_cast<const float4*>(pb + (((1 * 8 + q) << 2) | ct3) * 8192));
                af.x += v.x; af.y += v.y; af.z += v.z; af.w += v.w;
                v = __ldcg(reinterpret_cast<const float4*>(pb + (((2 * 8 + q) << 2) | ct3) * 8192));
                ag.x += v.x; ag.y += v.y; ag.z += v.z; ag.w += v.w;
                v = __ldcg(reinterpret_cast<const float4*>(pb + (((3 * 8 + q) << 2) | ct3) * 8192));
                ao.x += v.x; ao.y += v.y; ao.z += v.z; ao.w += v.w;
            }
            float4 hn;
            {
                float iv = sigf(ai.x + bi.x), fv = sigf(af.x + bf.x);
                float gv = tanhe(ag.x + bg4.x), ov = sigf(ao.x + bo.x);
                creg.x = fv * creg.x + iv * gv; hn.x = ov * tanhe(creg.x);
                iv = sigf(ai.y + bi.y); fv = sigf(af.y + bf.y);
                gv = tanhe(ag.y + bg4.y); ov = sigf(ao.y + bo.y);
                creg.y = fv * creg.y + iv * gv; hn.y = ov * tanhe(creg.y);
                iv = sigf(ai.z + bi.z); fv = sigf(af.z + bf.z);
                gv = tanhe(ag.z + bg4.z); ov = sigf(ao.z + bo.z);
                creg.z = fv * creg.z + iv * gv; hn.z = ov * tanhe(creg.z);
                iv = sigf(ai.w + bi.w); fv = sigf(af.w + bf.w);
                gv = tanhe(ag.w + bg4.w); ov = sigf(ao.w + bo.w);
                creg.w = fv * creg.w + iv * gv; hn.w = ov * tanhe(creg.w);
            }
            hlast = hn;
            const int ccl = ct3 * 128 + c4;
            __stcg(reinterpret_cast<float4*>(&g_hbuf[pn][bb * 512 + ccl]), hn);
            *reinterpret_cast<float4*>(&out[bb * (512 * 512) + t * 512 + ccl]) = hn;
        } else if (t + 1 < 512) {
            for (int i = tid - 64; i < 256; i += 192) {
                int b = i & 63, q = i >> 6;
                const float4* src = reinterpret_cast<const float4*>(
                    &x[b * (512 * 256) + (t + 1) * 256 + s1 * 64 + q * 16]);
                float* dst = &sA1[b * LD1 + q * 16];
                #pragma unroll
                for (int j = 0; j < 4; ++j) {
                    float4 v = __ldg(src + j);
                    dst[j * 4 + 0] = v.x; dst[j * 4 + 1] = v.y;
                    dst[j * 4 + 2] = v.z; dst[j * 4 + 3] = v.w;
                }
            }
        }
        __syncthreads();
        if (tid == 0) {
            __threadfence();
            redrel(&g_hcnt[ct3 * 64]);
        }
    }

    if (tid < 64) {
        const int bb = b0p + boff;
        const int ccl = ct3 * 128 + c4;
        *reinterpret_cast<float4*>(&out[16777216 + bb * 512 + ccl]) = hlast;
        *reinterpret_cast<float4*>(&out[16777216 + 32768 + bb * 512 + ccl]) = creg;
    }
    CWAIT();   // consume the final arrive before exit
}

extern "C" void kernel_launch(void* const* d_in, const int* in_sizes, int n_in,
                              void* d_out, int out_size) {
    const float* x      = (const float*)d_in[0];
    const float* Ws     = (const float*)d_in[1];
    const float* Us     = (const float*)d_in[2];
    const float* biases = (const float*)d_in[3];
    const float* Wc     = (const float*)d_in[4];
    const float* bc     = (const float*)d_in[5];
    float* out = (float*)d_out;
    (void)in_sizes; (void)n_in; (void)out_size;

    zero_kernel<<<32, 256>>>();
    cudaFuncSetAttribute(slstm_kernel, cudaFuncAttributeMaxDynamicSharedMemorySize,
                         SMEM_BYTES);
    slstm_kernel<<<NCTA, NTHR, SMEM_BYTES>>>(x, Ws, Us, biases, Wc, bc, out);
}